// round 1
// baseline (speedup 1.0000x reference)
#include <cuda_runtime.h>
#include <cuda_fp16.h>
#include <cstdint>

// Problem constants
#define IN_F   2048
#define OUT_F  2048
#define NROWS  8192   // 4 * 2048 tokens
#define INV_SQRT_D 0.022097086912079610f  // 1/sqrt(2048)

// GEMM tiling
#define BM 128
#define BN 128
#define BK 32
#define LDA (BK + 8)   // padded smem stride (halfs)
#define LDB (BK + 8)
#define NK  (IN_F / BK)

// Scratch (device globals: no dynamic allocation allowed)
__device__ __half Xh[(size_t)NROWS * IN_F];          // fp16 copy of x        (32 MB)
__device__ __half Wh[2 * (size_t)OUT_F * IN_F];      // [keys ; mu] fp16      (32 MB)
__device__ float  CompBuf[(size_t)NROWS * OUT_F];    // comp (x @ mu^T) fp32  (64 MB)

// ---------------------------------------------------------------------------
// Prep kernels
// ---------------------------------------------------------------------------
__global__ void prep_w(const float* __restrict__ mu, const float* __restrict__ sigma) {
    int i = blockIdx.x * blockDim.x + threadIdx.x;
    int stride = gridDim.x * blockDim.x;
    const int n = OUT_F * IN_F;
    for (; i < n; i += stride) {
        float m = mu[i];
        float s = sigma[i];
        // stable softplus
        float sp = (s > 20.f) ? s : log1pf(__expf(s));
        Wh[i]                      = __float2half_rn(m * sp);  // keys row block
        Wh[i + (size_t)OUT_F*IN_F] = __float2half_rn(m);       // mu row block
    }
}

__global__ void prep_x(const float* __restrict__ x) {
    // each thread converts 8 consecutive floats -> 8 halfs (16B store)
    size_t i = ((size_t)blockIdx.x * blockDim.x + threadIdx.x) * 8;
    const size_t n = (size_t)NROWS * IN_F;
    if (i >= n) return;
    float4 a = *(const float4*)(x + i);
    float4 b = *(const float4*)(x + i + 4);
    __half2 h0 = __floats2half2_rn(a.x, a.y);
    __half2 h1 = __floats2half2_rn(a.z, a.w);
    __half2 h2 = __floats2half2_rn(b.x, b.y);
    __half2 h3 = __floats2half2_rn(b.z, b.w);
    uint4 packed;
    packed.x = *(uint32_t*)&h0;
    packed.y = *(uint32_t*)&h1;
    packed.z = *(uint32_t*)&h2;
    packed.w = *(uint32_t*)&h3;
    *(uint4*)(Xh + i) = packed;
}

// ---------------------------------------------------------------------------
// GEMM: C[8192, 4096] = Xh @ Wh^T  (Wh rows: [0,2048)=keys, [2048,4096)=mu)
//   cols <  2048 -> scoresOut (scaled by 1/sqrt(d))
//   cols >= 2048 -> CompBuf
// ---------------------------------------------------------------------------
__device__ __forceinline__ void cp_async16(void* smem_ptr, const void* gmem_ptr) {
    uint32_t s = (uint32_t)__cvta_generic_to_shared(smem_ptr);
    asm volatile("cp.async.cg.shared.global [%0], [%1], 16;\n" :: "r"(s), "l"(gmem_ptr));
}
__device__ __forceinline__ void cp_commit()  { asm volatile("cp.async.commit_group;\n"); }
__device__ __forceinline__ void cp_wait1()   { asm volatile("cp.async.wait_group 1;\n"); }
__device__ __forceinline__ void cp_wait0()   { asm volatile("cp.async.wait_group 0;\n"); }

__device__ __forceinline__ void ldmatrix_x4(uint32_t* r, const __half* p) {
    uint32_t addr = (uint32_t)__cvta_generic_to_shared(p);
    asm volatile("ldmatrix.sync.aligned.m8n8.x4.shared.b16 {%0,%1,%2,%3}, [%4];\n"
                 : "=r"(r[0]), "=r"(r[1]), "=r"(r[2]), "=r"(r[3]) : "r"(addr));
}

__device__ __forceinline__ void mma16816(float* c, const uint32_t* a, const uint32_t* b) {
    asm volatile(
        "mma.sync.aligned.m16n8k16.row.col.f32.f16.f16.f32 "
        "{%0,%1,%2,%3}, {%4,%5,%6,%7}, {%8,%9}, {%0,%1,%2,%3};\n"
        : "+f"(c[0]), "+f"(c[1]), "+f"(c[2]), "+f"(c[3])
        : "r"(a[0]), "r"(a[1]), "r"(a[2]), "r"(a[3]), "r"(b[0]), "r"(b[1]));
}

__global__ __launch_bounds__(256) void gemm_kernel(float* __restrict__ scoresOut) {
    __shared__ __half sA[2][BM * LDA];
    __shared__ __half sB[2][BN * LDB];

    const int tid    = threadIdx.x;
    const int lane   = tid & 31;
    const int wid    = tid >> 5;
    const int warp_m = wid & 3;    // 4 warps along M  -> 32 rows each
    const int warp_n = wid >> 2;   // 2 warps along N  -> 64 cols each
    const int bm = blockIdx.y * BM;
    const int bn = blockIdx.x * BN;

    float acc[2][8][4];
    #pragma unroll
    for (int mt = 0; mt < 2; mt++)
        #pragma unroll
        for (int nt = 0; nt < 8; nt++)
            #pragma unroll
            for (int q = 0; q < 4; q++) acc[mt][nt][q] = 0.f;

    // global->smem loader mapping: 16B per cp.async
    const int lrow = tid >> 2;          // 0..63
    const int lk   = (tid & 3) * 8;     // 0,8,16,24 (halfs)
    const __half* gA = Xh + (size_t)bm * IN_F;
    const __half* gB = Wh + (size_t)bn * IN_F;

    // ldmatrix addressing (precomputed row/col within tile)
    const int a_row = (lane & 15);
    const int a_col = (lane >> 4) * 8;
    const int b_row = (lane & 7) + ((lane & 16) >> 1);
    const int b_col = (lane & 8) ? 8 : 0;

    #define LOAD_STAGE(st_, kt_) do {                                              \
        int k0 = (kt_) * BK;                                                       \
        _Pragma("unroll")                                                          \
        for (int j = 0; j < 2; j++) {                                              \
            int r = lrow + j * 64;                                                 \
            cp_async16(&sA[st_][r * LDA + lk], gA + (size_t)r * IN_F + k0 + lk);   \
            cp_async16(&sB[st_][r * LDB + lk], gB + (size_t)r * IN_F + k0 + lk);   \
        }                                                                          \
        cp_commit();                                                               \
    } while (0)

    LOAD_STAGE(0, 0);

    for (int kt = 0; kt < NK; kt++) {
        const int st = kt & 1;
        if (kt + 1 < NK) {
            LOAD_STAGE((kt + 1) & 1, kt + 1);
            cp_wait1();
        } else {
            cp_wait0();
        }
        __syncthreads();

        #pragma unroll
        for (int ks = 0; ks < 2; ks++) {
            uint32_t af[2][4];
            #pragma unroll
            for (int mt = 0; mt < 2; mt++) {
                int row = warp_m * 32 + mt * 16 + a_row;
                int col = ks * 16 + a_col;
                ldmatrix_x4(af[mt], &sA[st][row * LDA + col]);
            }
            uint32_t bf[8][2];
            #pragma unroll
            for (int bt = 0; bt < 4; bt++) {
                int nr  = warp_n * 64 + bt * 16 + b_row;
                int col = ks * 16 + b_col;
                uint32_t r[4];
                ldmatrix_x4(r, &sB[st][nr * LDB + col]);
                bf[2*bt  ][0] = r[0]; bf[2*bt  ][1] = r[1];
                bf[2*bt+1][0] = r[2]; bf[2*bt+1][1] = r[3];
            }
            #pragma unroll
            for (int mt = 0; mt < 2; mt++)
                #pragma unroll
                for (int nt = 0; nt < 8; nt++)
                    mma16816(acc[mt][nt], af[mt], bf[nt]);
        }
        __syncthreads();
    }

    // Epilogue: route to scores (scaled) or comp scratch
    const bool isScores = (bn < OUT_F);
    float* dst = isScores ? scoresOut : CompBuf;
    const float scale = isScores ? INV_SQRT_D : 1.0f;
    const int colbase = bn & (OUT_F - 1);

    #pragma unroll
    for (int mt = 0; mt < 2; mt++) {
        #pragma unroll
        for (int nt = 0; nt < 8; nt++) {
            int r = bm + warp_m * 32 + mt * 16 + (lane >> 2);
            int c = colbase + warp_n * 64 + nt * 8 + (lane & 3) * 2;
            float2 v0 = make_float2(acc[mt][nt][0] * scale, acc[mt][nt][1] * scale);
            float2 v1 = make_float2(acc[mt][nt][2] * scale, acc[mt][nt][3] * scale);
            *(float2*)&dst[(size_t)r * OUT_F + c]       = v0;
            *(float2*)&dst[(size_t)(r + 8) * OUT_F + c] = v1;
        }
    }
}

// ---------------------------------------------------------------------------
// Mask epilogue: masked = comp * relu(scores - gate); write to out0 and out2
// ---------------------------------------------------------------------------
__global__ void mask_kernel(const float* __restrict__ scores,
                            const float* __restrict__ gate,
                            float* __restrict__ out0,
                            float* __restrict__ out2) {
    size_t i = (size_t)blockIdx.x * blockDim.x + threadIdx.x;
    const size_t n4 = (size_t)NROWS * OUT_F / 4;
    if (i >= n4) return;
    float4 s = ((const float4*)scores)[i];
    float4 c = ((const float4*)CompBuf)[i];
    int col4 = (int)((i * 4) & (OUT_F - 1)) >> 2;
    float4 g = ((const float4*)gate)[col4];
    float4 m;
    m.x = c.x * fmaxf(s.x - g.x, 0.f);
    m.y = c.y * fmaxf(s.y - g.y, 0.f);
    m.z = c.z * fmaxf(s.z - g.z, 0.f);
    m.w = c.w * fmaxf(s.w - g.w, 0.f);
    ((float4*)out0)[i] = m;
    ((float4*)out2)[i] = m;
}

// ---------------------------------------------------------------------------
// Launch
// ---------------------------------------------------------------------------
extern "C" void kernel_launch(void* const* d_in, const int* in_sizes, int n_in,
                              void* d_out, int out_size) {
    const float* x     = (const float*)d_in[0];   // [4,2048,2048]
    const float* mu    = (const float*)d_in[1];   // [2048,2048]
    const float* sigma = (const float*)d_in[2];   // [2048,2048]
    const float* gate  = (const float*)d_in[3];   // [2048]

    float* out  = (float*)d_out;
    float* out0 = out;                                   // final_output
    float* out1 = out + (size_t)NROWS * OUT_F;           // scores
    float* out2 = out + 2 * (size_t)NROWS * OUT_F;       // masked_output

    prep_w<<<512, 256>>>(mu, sigma);

    {
        size_t n8 = (size_t)NROWS * IN_F / 8;            // 2,097,152 threads
        prep_x<<<(unsigned)((n8 + 255) / 256), 256>>>(x);
    }

    dim3 grid(2 * OUT_F / BN, NROWS / BM);               // (32, 64)
    gemm_kernel<<<grid, 256>>>(out1);

    {
        size_t n4 = (size_t)NROWS * OUT_F / 4;
        mask_kernel<<<(unsigned)((n4 + 255) / 256), 256>>>(out1, gate, out0, out2);
    }
}

// round 3
// speedup vs baseline: 1.3004x; 1.3004x over previous
#include <cuda_runtime.h>
#include <cuda_fp16.h>
#include <cstdint>

// Problem constants
#define IN_F   2048
#define OUT_F  2048
#define NROWS  8192
#define INV_SQRT_D 0.022097086912079610f

// Tiling
#define BM 128
#define BN 128                  // output cols per CTA (keys AND mu computed)
#define KB 64                   // K halfs per stage = 128 bytes per row
#define NSTG (IN_F / KB)        // 32
#define NBUF 4
#define A_BYTES (BM * 128)      // 16384
#define B_BYTES (2 * BN * 128)  // 32768 (keys 128 rows + mu 128 rows)
#define STAGE_BYTES (A_BYTES + B_BYTES)   // 49152
#define SMEM_TOTAL (NBUF * STAGE_BYTES)   // 196608

// Scratch globals (no dynamic allocation allowed)
__device__ __half Xh[(size_t)NROWS * IN_F];        // fp16 x        (32 MB)
__device__ __half Wh[2 * (size_t)OUT_F * IN_F];    // [keys ; mu]   (32 MB)

// ---------------------------------------------------------------------------
// PTX helpers
// ---------------------------------------------------------------------------
__device__ __forceinline__ void cp_async16(uint32_t smem_addr, const void* gmem_ptr) {
    asm volatile("cp.async.cg.shared.global [%0], [%1], 16;\n" :: "r"(smem_addr), "l"(gmem_ptr));
}
__device__ __forceinline__ void cp_commit() { asm volatile("cp.async.commit_group;\n"); }
template <int N>
__device__ __forceinline__ void cp_wait() { asm volatile("cp.async.wait_group %0;\n" :: "n"(N)); }

__device__ __forceinline__ void ldmatrix_x4(uint32_t* r, uint32_t addr) {
    asm volatile("ldmatrix.sync.aligned.m8n8.x4.shared.b16 {%0,%1,%2,%3}, [%4];\n"
                 : "=r"(r[0]), "=r"(r[1]), "=r"(r[2]), "=r"(r[3]) : "r"(addr));
}

__device__ __forceinline__ void mma16816(float* c, const uint32_t* a, const uint32_t* b) {
    asm volatile(
        "mma.sync.aligned.m16n8k16.row.col.f32.f16.f16.f32 "
        "{%0,%1,%2,%3}, {%4,%5,%6,%7}, {%8,%9}, {%0,%1,%2,%3};\n"
        : "+f"(c[0]), "+f"(c[1]), "+f"(c[2]), "+f"(c[3])
        : "r"(a[0]), "r"(a[1]), "r"(a[2]), "r"(a[3]), "r"(b[0]), "r"(b[1]));
}

// ---------------------------------------------------------------------------
// Prep kernels (f32 -> f16)
// ---------------------------------------------------------------------------
__global__ void prep_w(const float* __restrict__ mu, const float* __restrict__ sigma) {
    int i = blockIdx.x * blockDim.x + threadIdx.x;
    int stride = gridDim.x * blockDim.x;
    const int n = OUT_F * IN_F;
    for (; i < n; i += stride) {
        float m = mu[i];
        float s = sigma[i];
        float sp = (s > 20.f) ? s : log1pf(__expf(s));
        Wh[i]                        = __float2half_rn(m * sp);  // keys
        Wh[i + (size_t)OUT_F * IN_F] = __float2half_rn(m);       // mu
    }
}

__global__ void prep_x(const float* __restrict__ x) {
    size_t i = ((size_t)blockIdx.x * blockDim.x + threadIdx.x) * 8;
    if (i >= (size_t)NROWS * IN_F) return;
    float4 a = *(const float4*)(x + i);
    float4 b = *(const float4*)(x + i + 4);
    __half2 h0 = __floats2half2_rn(a.x, a.y);
    __half2 h1 = __floats2half2_rn(a.z, a.w);
    __half2 h2 = __floats2half2_rn(b.x, b.y);
    __half2 h3 = __floats2half2_rn(b.z, b.w);
    uint4 p;
    p.x = *(uint32_t*)&h0; p.y = *(uint32_t*)&h1;
    p.z = *(uint32_t*)&h2; p.w = *(uint32_t*)&h3;
    *(uint4*)(Xh + i) = p;
}

// ---------------------------------------------------------------------------
// Fused GEMM: per CTA, 128x128 tile of scores AND comp; epilogue masks in-reg.
// ---------------------------------------------------------------------------
__device__ __forceinline__ void load_stage(uint32_t smem_u32, int buf, int stage,
                                           int bm, int bn, int tid) {
    const int k0 = stage * KB;
    const uint32_t sA = smem_u32 + buf * STAGE_BYTES;
    const uint32_t sB = sA + A_BYTES;
    // A: 1024 chunks of 16B (128 rows x 8 chunks)
    #pragma unroll
    for (int i = 0; i < 4; i++) {
        int q = tid + 256 * i;
        int r = q >> 3;
        int c = q & 7;
        cp_async16(sA + r * 128 + ((c ^ (r & 7)) * 16),
                   Xh + (size_t)(bm + r) * IN_F + k0 + c * 8);
    }
    // B: 2048 chunks (256 rows: 0..127 keys, 128..255 mu)
    #pragma unroll
    for (int i = 0; i < 8; i++) {
        int q = tid + 256 * i;
        int r = q >> 3;
        int c = q & 7;
        int grow = (r < 128) ? (bn + r) : (OUT_F - 128 + bn + r);
        cp_async16(sB + r * 128 + ((c ^ (r & 7)) * 16),
                   Wh + (size_t)grow * IN_F + k0 + c * 8);
    }
    cp_commit();
}

__global__ __launch_bounds__(256, 1) void gemm_fused(
    const float* __restrict__ gate,
    float* __restrict__ outFinal,
    float* __restrict__ outScores,
    float* __restrict__ outMasked)
{
    extern __shared__ char smem[];
    __shared__ float gateS[BN];
    const uint32_t smem_u32 = (uint32_t)__cvta_generic_to_shared(smem);

    const int tid    = threadIdx.x;
    const int lane   = tid & 31;
    const int wid    = tid >> 5;
    const int warp_m = wid >> 2;      // 0..1 -> 64 rows each
    const int warp_n = wid & 3;       // 0..3 -> 32 cols each
    const int bm = blockIdx.y * BM;
    const int bn = blockIdx.x * BN;

    if (tid < BN) gateS[tid] = gate[bn + tid];

    float acck[4][4][4];   // keys-scores accum: mt x nt x 4
    float accm[4][4][4];   // mu-comp accum
    #pragma unroll
    for (int mt = 0; mt < 4; mt++)
        #pragma unroll
        for (int nt = 0; nt < 4; nt++)
            #pragma unroll
            for (int q = 0; q < 4; q++) { acck[mt][nt][q] = 0.f; accm[mt][nt][q] = 0.f; }

    // Prologue: fill 3 stages
    load_stage(smem_u32, 0, 0, bm, bn, tid);
    load_stage(smem_u32, 1, 1, bm, bn, tid);
    load_stage(smem_u32, 2, 2, bm, bn, tid);

    // ldmatrix lane addressing
    const int a_row = lane & 15;             // + warp_m*64 + mt*16
    const int a_sel = lane >> 4;             // chunk low bit
    const int b_row = (lane & 7) + ((lane & 16) >> 1);
    const int b_sel = (lane & 8) ? 1 : 0;

    for (int s = 0; s < NSTG; s++) {
        if (s <= NSTG - 3)      cp_wait<2>();
        else if (s == NSTG - 2) cp_wait<1>();
        else                    cp_wait<0>();
        __syncthreads();

        if (s + 3 < NSTG) load_stage(smem_u32, (s + 3) & 3, s + 3, bm, bn, tid);

        const uint32_t sA = smem_u32 + (s & 3) * STAGE_BYTES;
        const uint32_t sB = sA + A_BYTES;

        #pragma unroll
        for (int ks = 0; ks < 4; ks++) {
            // A fragments: 4 tiles of 16 rows
            uint32_t af[4][4];
            #pragma unroll
            for (int mt = 0; mt < 4; mt++) {
                int row = warp_m * 64 + mt * 16 + a_row;
                int ch  = (ks * 2 + a_sel) ^ (row & 7);
                ldmatrix_x4(af[mt], sA + row * 128 + ch * 16);
            }
            // B fragments: keys (rows warp_n*32..) and mu (rows 128+warp_n*32..)
            uint32_t bk[4][2], bmu[4][2];
            #pragma unroll
            for (int bt = 0; bt < 2; bt++) {
                {
                    int row = warp_n * 32 + bt * 16 + b_row;
                    int ch  = (ks * 2 + b_sel) ^ (row & 7);
                    uint32_t r[4];
                    ldmatrix_x4(r, sB + row * 128 + ch * 16);
                    bk[2*bt  ][0] = r[0]; bk[2*bt  ][1] = r[1];
                    bk[2*bt+1][0] = r[2]; bk[2*bt+1][1] = r[3];
                }
                {
                    int row = 128 + warp_n * 32 + bt * 16 + b_row;
                    int ch  = (ks * 2 + b_sel) ^ (row & 7);
                    uint32_t r[4];
                    ldmatrix_x4(r, sB + row * 128 + ch * 16);
                    bmu[2*bt  ][0] = r[0]; bmu[2*bt  ][1] = r[1];
                    bmu[2*bt+1][0] = r[2]; bmu[2*bt+1][1] = r[3];
                }
            }
            #pragma unroll
            for (int mt = 0; mt < 4; mt++) {
                #pragma unroll
                for (int nt = 0; nt < 4; nt++) {
                    mma16816(acck[mt][nt], af[mt], bk[nt]);
                    mma16816(accm[mt][nt], af[mt], bmu[nt]);
                }
            }
        }
        __syncthreads();
    }

    // Fused epilogue: scores, masked = comp * relu(scores - gate)
    #pragma unroll
    for (int mt = 0; mt < 4; mt++) {
        int r0 = bm + warp_m * 64 + mt * 16 + (lane >> 2);
        #pragma unroll
        for (int nt = 0; nt < 4; nt++) {
            int cl = warp_n * 32 + nt * 8 + (lane & 3) * 2;
            int c  = bn + cl;
            float g0 = gateS[cl], g1 = gateS[cl + 1];

            float s0 = acck[mt][nt][0] * INV_SQRT_D;
            float s1 = acck[mt][nt][1] * INV_SQRT_D;
            float m0 = accm[mt][nt][0] * fmaxf(s0 - g0, 0.f);
            float m1 = accm[mt][nt][1] * fmaxf(s1 - g1, 0.f);
            size_t o0 = (size_t)r0 * OUT_F + c;
            *(float2*)(outScores + o0) = make_float2(s0, s1);
            *(float2*)(outFinal  + o0) = make_float2(m0, m1);
            *(float2*)(outMasked + o0) = make_float2(m0, m1);

            float s2 = acck[mt][nt][2] * INV_SQRT_D;
            float s3 = acck[mt][nt][3] * INV_SQRT_D;
            float m2 = accm[mt][nt][2] * fmaxf(s2 - g0, 0.f);
            float m3 = accm[mt][nt][3] * fmaxf(s3 - g1, 0.f);
            size_t o1 = (size_t)(r0 + 8) * OUT_F + c;
            *(float2*)(outScores + o1) = make_float2(s2, s3);
            *(float2*)(outFinal  + o1) = make_float2(m2, m3);
            *(float2*)(outMasked + o1) = make_float2(m2, m3);
        }
    }
}

// ---------------------------------------------------------------------------
// Launch
// ---------------------------------------------------------------------------
extern "C" void kernel_launch(void* const* d_in, const int* in_sizes, int n_in,
                              void* d_out, int out_size) {
    const float* x     = (const float*)d_in[0];
    const float* mu    = (const float*)d_in[1];
    const float* sigma = (const float*)d_in[2];
    const float* gate  = (const float*)d_in[3];

    float* out  = (float*)d_out;
    float* out0 = out;                               // final_output
    float* out1 = out + (size_t)NROWS * OUT_F;       // scores
    float* out2 = out + 2 * (size_t)NROWS * OUT_F;   // masked_output

    prep_w<<<512, 256>>>(mu, sigma);
    {
        size_t n8 = (size_t)NROWS * IN_F / 8;
        prep_x<<<(unsigned)((n8 + 255) / 256), 256>>>(x);
    }

    cudaFuncSetAttribute(gemm_fused, cudaFuncAttributeMaxDynamicSharedMemorySize, SMEM_TOTAL);
    dim3 grid(OUT_F / BN, NROWS / BM);               // (16, 64) = 1024 CTAs
    gemm_fused<<<grid, 256, SMEM_TOTAL>>>(gate, out0, out1, out2);
}

// round 4
// speedup vs baseline: 1.4807x; 1.1387x over previous
#include <cuda_runtime.h>
#include <cuda_fp16.h>
#include <cstdint>

// Problem constants
#define IN_F   2048
#define OUT_F  2048
#define NROWS  8192
#define INV_SQRT_D 0.022097086912079610f

// Tiling
#define BM 128
#define BN 128
#define KB 64                       // K halfs per stage (one 16KB tile deep)
#define NSTG (IN_F / KB)            // 32
#define TILE_HALFS 8192             // 128 rows * 64 halfs
#define TILE_BYTES 16384
#define STAGE_BYTES 49152           // A + Bkeys + Bmu
#define NBUF 4
#define SMEM_TOTAL (NBUF * STAGE_BYTES)   // 196608
#define MU_BASE ((size_t)OUT_F * IN_F)    // half offset of mu block in Wh

// Scratch globals: TILED + SWIZZLED layouts.
// Xh: tile(mblk, kst) at (mblk*NSTG+kst)*8192 halfs;
//     inner: row r(0..127), chunk c(0..7): half off = r*64 + ((c^(r&7))*8)
__device__ __align__(1024) __half Xh[(size_t)NROWS * IN_F];
__device__ __align__(1024) __half Wh[2 * (size_t)OUT_F * IN_F];  // [keys tiles ; mu tiles]

// ---------------------------------------------------------------------------
// PTX helpers
// ---------------------------------------------------------------------------
__device__ __forceinline__ void ldmatrix_x4(uint32_t* r, uint32_t addr) {
    asm volatile("ldmatrix.sync.aligned.m8n8.x4.shared.b16 {%0,%1,%2,%3}, [%4];\n"
                 : "=r"(r[0]), "=r"(r[1]), "=r"(r[2]), "=r"(r[3]) : "r"(addr));
}

__device__ __forceinline__ void mma16816(float* c, const uint32_t* a, const uint32_t* b) {
    asm volatile(
        "mma.sync.aligned.m16n8k16.row.col.f32.f16.f16.f32 "
        "{%0,%1,%2,%3}, {%4,%5,%6,%7}, {%8,%9}, {%0,%1,%2,%3};\n"
        : "+f"(c[0]), "+f"(c[1]), "+f"(c[2]), "+f"(c[3])
        : "r"(a[0]), "r"(a[1]), "r"(a[2]), "r"(a[3]), "r"(b[0]), "r"(b[1]));
}

__device__ __forceinline__ void mbar_init(uint32_t addr, uint32_t count) {
    asm volatile("mbarrier.init.shared.b64 [%0], %1;" :: "r"(addr), "r"(count) : "memory");
}
__device__ __forceinline__ void mbar_expect_tx(uint32_t addr, uint32_t bytes) {
    asm volatile("mbarrier.arrive.expect_tx.shared.b64 _, [%0], %1;"
                 :: "r"(addr), "r"(bytes) : "memory");
}
__device__ __forceinline__ void mbar_wait(uint32_t addr, uint32_t parity) {
    asm volatile(
        "{\n\t.reg .pred P;\n\t"
        "WL_%=:\n\t"
        "mbarrier.try_wait.parity.shared.b64 P, [%0], %1, 0x989680;\n\t"
        "@!P bra WL_%=;\n\t}"
        :: "r"(addr), "r"(parity) : "memory");
}
__device__ __forceinline__ void bulk_g2s(uint32_t dst, const void* src,
                                         uint32_t bytes, uint32_t mbar) {
    asm volatile(
        "cp.async.bulk.shared::cluster.global.mbarrier::complete_tx::bytes [%0], [%1], %2, [%3];"
        :: "r"(dst), "l"(src), "r"(bytes), "r"(mbar) : "memory");
}

// ---------------------------------------------------------------------------
// Prep kernels: f32 -> f16 into tiled+swizzled layout
// ---------------------------------------------------------------------------
__device__ __forceinline__ size_t tiled_off(int row, int k8 /*16B chunk idx*/) {
    // blk index uses caller-provided row base; here row is global row within matrix
    int blk  = row >> 7;
    int rloc = row & 127;
    int kst  = k8 >> 3;
    int c    = k8 & 7;
    return (size_t)(blk * NSTG + kst) * TILE_HALFS + rloc * 64 + ((c ^ (rloc & 7)) * 8);
}

__global__ void prep_w(const float* __restrict__ mu, const float* __restrict__ sigma) {
    size_t q = (size_t)blockIdx.x * blockDim.x + threadIdx.x;   // one 16B chunk (8 elems)
    size_t i = q * 8;
    if (i >= (size_t)OUT_F * IN_F) return;
    int row = (int)(i >> 11);
    int k8  = (int)((i & 2047) >> 3);

    float4 m0 = *(const float4*)(mu + i);
    float4 m1 = *(const float4*)(mu + i + 4);
    float4 s0 = *(const float4*)(sigma + i);
    float4 s1 = *(const float4*)(sigma + i + 4);

    float mf[8] = {m0.x, m0.y, m0.z, m0.w, m1.x, m1.y, m1.z, m1.w};
    float sf[8] = {s0.x, s0.y, s0.z, s0.w, s1.x, s1.y, s1.z, s1.w};

    __half kh[8], mh[8];
    #pragma unroll
    for (int j = 0; j < 8; j++) {
        float s  = sf[j];
        float sp = (s > 20.f) ? s : log1pf(__expf(s));
        kh[j] = __float2half_rn(mf[j] * sp);
        mh[j] = __float2half_rn(mf[j]);
    }
    size_t dst = tiled_off(row, k8);
    *(uint4*)(Wh + dst)           = *(uint4*)kh;
    *(uint4*)(Wh + MU_BASE + dst) = *(uint4*)mh;
}

__global__ void prep_x(const float* __restrict__ x) {
    size_t q = (size_t)blockIdx.x * blockDim.x + threadIdx.x;
    size_t i = q * 8;
    if (i >= (size_t)NROWS * IN_F) return;
    int row = (int)(i >> 11);
    int k8  = (int)((i & 2047) >> 3);

    float4 a = *(const float4*)(x + i);
    float4 b = *(const float4*)(x + i + 4);
    __half2 h0 = __floats2half2_rn(a.x, a.y);
    __half2 h1 = __floats2half2_rn(a.z, a.w);
    __half2 h2 = __floats2half2_rn(b.x, b.y);
    __half2 h3 = __floats2half2_rn(b.z, b.w);
    uint4 p;
    p.x = *(uint32_t*)&h0; p.y = *(uint32_t*)&h1;
    p.z = *(uint32_t*)&h2; p.w = *(uint32_t*)&h3;
    *(uint4*)(Xh + tiled_off(row, k8)) = p;
}

// ---------------------------------------------------------------------------
// Fused GEMM with bulk-copy pipeline
// ---------------------------------------------------------------------------
__device__ __forceinline__ void issue_stage(uint32_t smem_u32, uint32_t mbar_u32, int s,
                                            const __half* gA, const __half* gBk,
                                            const __half* gBm) {
    const int b = s & 3;
    const uint32_t mb  = mbar_u32 + b * 8;
    const uint32_t dst = smem_u32 + b * STAGE_BYTES;
    mbar_expect_tx(mb, STAGE_BYTES);
    bulk_g2s(dst,         gA  + (size_t)s * TILE_HALFS, TILE_BYTES, mb);
    bulk_g2s(dst + 16384, gBk + (size_t)s * TILE_HALFS, TILE_BYTES, mb);
    bulk_g2s(dst + 32768, gBm + (size_t)s * TILE_HALFS, TILE_BYTES, mb);
}

__global__ __launch_bounds__(256, 1) void gemm_fused(
    const float* __restrict__ gate,
    float* __restrict__ outFinal,
    float* __restrict__ outScores,
    float* __restrict__ outMasked)
{
    extern __shared__ char smem[];
    __shared__ float gateS[BN];
    __shared__ __align__(8) uint64_t mbarS[NBUF];

    const uint32_t smem_u32 = (uint32_t)__cvta_generic_to_shared(smem);
    const uint32_t mbar_u32 = (uint32_t)__cvta_generic_to_shared(mbarS);

    const int tid    = threadIdx.x;
    const int lane   = tid & 31;
    const int wid    = tid >> 5;
    const int warp_m = wid >> 2;      // 0..1 -> 64 rows
    const int warp_n = wid & 3;       // 0..3 -> 32 cols
    const int mblk = blockIdx.y;
    const int nblk = blockIdx.x;
    const int bm = mblk * BM;
    const int bn = nblk * BN;

    if (tid < BN) gateS[tid] = gate[bn + tid];
    if (tid == 0) {
        #pragma unroll
        for (int b = 0; b < NBUF; b++) mbar_init(mbar_u32 + b * 8, 1);
    }
    __syncthreads();

    const __half* gA  = Xh + (size_t)mblk * NSTG * TILE_HALFS;
    const __half* gBk = Wh + (size_t)nblk * NSTG * TILE_HALFS;
    const __half* gBm = gBk + MU_BASE;

    if (tid == 0) {
        issue_stage(smem_u32, mbar_u32, 0, gA, gBk, gBm);
        issue_stage(smem_u32, mbar_u32, 1, gA, gBk, gBm);
        issue_stage(smem_u32, mbar_u32, 2, gA, gBk, gBm);
    }

    float acck[4][4][4], accm[4][4][4];
    #pragma unroll
    for (int mt = 0; mt < 4; mt++)
        #pragma unroll
        for (int nt = 0; nt < 4; nt++)
            #pragma unroll
            for (int q = 0; q < 4; q++) { acck[mt][nt][q] = 0.f; accm[mt][nt][q] = 0.f; }

    const int a_row = lane & 15;
    const int a_sel = lane >> 4;
    const int b_row = (lane & 7) + ((lane & 16) >> 1);
    const int b_sel = (lane & 8) ? 1 : 0;

    for (int s = 0; s < NSTG; s++) {
        mbar_wait(mbar_u32 + (s & 3) * 8, (s >> 2) & 1);
        __syncthreads();   // all warps done reading buffer (s-1)&3 == (s+3)&3
        if (tid == 0 && s + 3 < NSTG)
            issue_stage(smem_u32, mbar_u32, s + 3, gA, gBk, gBm);

        const uint32_t sA  = smem_u32 + (s & 3) * STAGE_BYTES;
        const uint32_t sBk = sA + 16384;
        const uint32_t sBm = sA + 32768;

        #pragma unroll
        for (int ks = 0; ks < 4; ks++) {
            uint32_t af[4][4];
            #pragma unroll
            for (int mt = 0; mt < 4; mt++) {
                int row = warp_m * 64 + mt * 16 + a_row;
                int ch  = (ks * 2 + a_sel) ^ (row & 7);
                ldmatrix_x4(af[mt], sA + row * 128 + ch * 16);
            }
            uint32_t bk[4][2], bmu[4][2];
            #pragma unroll
            for (int bt = 0; bt < 2; bt++) {
                int row = warp_n * 32 + bt * 16 + b_row;
                int ch  = (ks * 2 + b_sel) ^ (row & 7);
                uint32_t r[4];
                ldmatrix_x4(r, sBk + row * 128 + ch * 16);
                bk[2*bt  ][0] = r[0]; bk[2*bt  ][1] = r[1];
                bk[2*bt+1][0] = r[2]; bk[2*bt+1][1] = r[3];
                uint32_t t[4];
                ldmatrix_x4(t, sBm + row * 128 + ch * 16);
                bmu[2*bt  ][0] = t[0]; bmu[2*bt  ][1] = t[1];
                bmu[2*bt+1][0] = t[2]; bmu[2*bt+1][1] = t[3];
            }
            #pragma unroll
            for (int mt = 0; mt < 4; mt++) {
                #pragma unroll
                for (int nt = 0; nt < 4; nt++) {
                    mma16816(acck[mt][nt], af[mt], bk[nt]);
                    mma16816(accm[mt][nt], af[mt], bmu[nt]);
                }
            }
        }
    }

    // Fused epilogue
    #pragma unroll
    for (int mt = 0; mt < 4; mt++) {
        int r0 = bm + warp_m * 64 + mt * 16 + (lane >> 2);
        #pragma unroll
        for (int nt = 0; nt < 4; nt++) {
            int cl = warp_n * 32 + nt * 8 + (lane & 3) * 2;
            int c  = bn + cl;
            float g0 = gateS[cl], g1 = gateS[cl + 1];

            float s0 = acck[mt][nt][0] * INV_SQRT_D;
            float s1 = acck[mt][nt][1] * INV_SQRT_D;
            float m0 = accm[mt][nt][0] * fmaxf(s0 - g0, 0.f);
            float m1 = accm[mt][nt][1] * fmaxf(s1 - g1, 0.f);
            size_t o0 = (size_t)r0 * OUT_F + c;
            *(float2*)(outScores + o0) = make_float2(s0, s1);
            *(float2*)(outFinal  + o0) = make_float2(m0, m1);
            *(float2*)(outMasked + o0) = make_float2(m0, m1);

            float s2 = acck[mt][nt][2] * INV_SQRT_D;
            float s3 = acck[mt][nt][3] * INV_SQRT_D;
            float m2 = accm[mt][nt][2] * fmaxf(s2 - g0, 0.f);
            float m3 = accm[mt][nt][3] * fmaxf(s3 - g1, 0.f);
            size_t o1 = (size_t)(r0 + 8) * OUT_F + c;
            *(float2*)(outScores + o1) = make_float2(s2, s3);
            *(float2*)(outFinal  + o1) = make_float2(m2, m3);
            *(float2*)(outMasked + o1) = make_float2(m2, m3);
        }
    }
}

// ---------------------------------------------------------------------------
// Launch
// ---------------------------------------------------------------------------
extern "C" void kernel_launch(void* const* d_in, const int* in_sizes, int n_in,
                              void* d_out, int out_size) {
    const float* x     = (const float*)d_in[0];
    const float* mu    = (const float*)d_in[1];
    const float* sigma = (const float*)d_in[2];
    const float* gate  = (const float*)d_in[3];

    float* out  = (float*)d_out;
    float* out0 = out;                               // final_output
    float* out1 = out + (size_t)NROWS * OUT_F;       // scores
    float* out2 = out + 2 * (size_t)NROWS * OUT_F;   // masked_output

    prep_w<<<(OUT_F * IN_F / 8 + 255) / 256, 256>>>(mu, sigma);
    prep_x<<<(unsigned)(((size_t)NROWS * IN_F / 8 + 255) / 256), 256>>>(x);

    cudaFuncSetAttribute(gemm_fused, cudaFuncAttributeMaxDynamicSharedMemorySize, SMEM_TOTAL);
    dim3 grid(OUT_F / BN, NROWS / BM);               // (16, 64) = 1024 CTAs
    gemm_fused<<<grid, 256, SMEM_TOTAL>>>(gate, out0, out1, out2);
}

// round 5
// speedup vs baseline: 1.6707x; 1.1283x over previous
#include <cuda_runtime.h>
#include <cuda_fp16.h>
#include <cstdint>

// Problem constants
#define IN_F   2048
#define OUT_F  2048
#define NROWS  8192
#define INV_SQRT_D 0.022097086912079610f

// Tiling
#define BM 128
#define BN 128
#define KB 64                       // K halfs per stage
#define NSTG (IN_F / KB)            // 32
#define TILE_HALFS 8192             // 128 rows * 64 halfs
#define TILE_BYTES 16384
#define STAGE_BYTES 49152           // A + Bkeys + Bmu
#define NBUF 4
#define SMEM_TOTAL (NBUF * STAGE_BYTES)   // 196608
#define MU_BASE ((size_t)OUT_F * IN_F)

// Scratch globals: TILED + SWIZZLED layouts (see tiled_off)
__device__ __align__(1024) __half Xh[(size_t)NROWS * IN_F];
__device__ __align__(1024) __half Wh[2 * (size_t)OUT_F * IN_F];  // [keys tiles ; mu tiles]

// ---------------------------------------------------------------------------
// PTX helpers
// ---------------------------------------------------------------------------
__device__ __forceinline__ void ldmatrix_x4(uint32_t* r, uint32_t addr) {
    asm volatile("ldmatrix.sync.aligned.m8n8.x4.shared.b16 {%0,%1,%2,%3}, [%4];\n"
                 : "=r"(r[0]), "=r"(r[1]), "=r"(r[2]), "=r"(r[3]) : "r"(addr));
}

__device__ __forceinline__ void mma16816(float* c, const uint32_t* a, const uint32_t* b) {
    asm volatile(
        "mma.sync.aligned.m16n8k16.row.col.f32.f16.f16.f32 "
        "{%0,%1,%2,%3}, {%4,%5,%6,%7}, {%8,%9}, {%0,%1,%2,%3};\n"
        : "+f"(c[0]), "+f"(c[1]), "+f"(c[2]), "+f"(c[3])
        : "r"(a[0]), "r"(a[1]), "r"(a[2]), "r"(a[3]), "r"(b[0]), "r"(b[1]));
}

__device__ __forceinline__ void mbar_init(uint32_t addr, uint32_t count) {
    asm volatile("mbarrier.init.shared.b64 [%0], %1;" :: "r"(addr), "r"(count) : "memory");
}
__device__ __forceinline__ void mbar_expect_tx(uint32_t addr, uint32_t bytes) {
    asm volatile("mbarrier.arrive.expect_tx.shared.b64 _, [%0], %1;"
                 :: "r"(addr), "r"(bytes) : "memory");
}
__device__ __forceinline__ void mbar_arrive(uint32_t addr) {
    asm volatile("mbarrier.arrive.shared.b64 _, [%0];" :: "r"(addr) : "memory");
}
__device__ __forceinline__ void mbar_wait(uint32_t addr, uint32_t parity) {
    asm volatile(
        "{\n\t.reg .pred P;\n\t"
        "WL_%=:\n\t"
        "mbarrier.try_wait.parity.shared.b64 P, [%0], %1, 0x989680;\n\t"
        "@!P bra WL_%=;\n\t}"
        :: "r"(addr), "r"(parity) : "memory");
}
__device__ __forceinline__ void bulk_g2s(uint32_t dst, const void* src,
                                         uint32_t bytes, uint32_t mbar) {
    asm volatile(
        "cp.async.bulk.shared::cluster.global.mbarrier::complete_tx::bytes [%0], [%1], %2, [%3];"
        :: "r"(dst), "l"(src), "r"(bytes), "r"(mbar) : "memory");
}

// ---------------------------------------------------------------------------
// Prep kernels: f32 -> f16 into tiled+swizzled layout
// ---------------------------------------------------------------------------
__device__ __forceinline__ size_t tiled_off(int row, int k8) {
    int blk  = row >> 7;
    int rloc = row & 127;
    int kst  = k8 >> 3;
    int c    = k8 & 7;
    return (size_t)(blk * NSTG + kst) * TILE_HALFS + rloc * 64 + ((c ^ (rloc & 7)) * 8);
}

__global__ void prep_w(const float* __restrict__ mu, const float* __restrict__ sigma) {
    size_t q = (size_t)blockIdx.x * blockDim.x + threadIdx.x;
    size_t i = q * 8;
    if (i >= (size_t)OUT_F * IN_F) return;
    int row = (int)(i >> 11);
    int k8  = (int)((i & 2047) >> 3);

    float4 m0 = *(const float4*)(mu + i);
    float4 m1 = *(const float4*)(mu + i + 4);
    float4 s0 = *(const float4*)(sigma + i);
    float4 s1 = *(const float4*)(sigma + i + 4);

    float mf[8] = {m0.x, m0.y, m0.z, m0.w, m1.x, m1.y, m1.z, m1.w};
    float sf[8] = {s0.x, s0.y, s0.z, s0.w, s1.x, s1.y, s1.z, s1.w};

    __half kh[8], mh[8];
    #pragma unroll
    for (int j = 0; j < 8; j++) {
        float s  = sf[j];
        float sp = (s > 20.f) ? s : log1pf(__expf(s));
        kh[j] = __float2half_rn(mf[j] * sp);
        mh[j] = __float2half_rn(mf[j]);
    }
    size_t dst = tiled_off(row, k8);
    *(uint4*)(Wh + dst)           = *(uint4*)kh;
    *(uint4*)(Wh + MU_BASE + dst) = *(uint4*)mh;
}

__global__ void prep_x(const float* __restrict__ x) {
    size_t q = (size_t)blockIdx.x * blockDim.x + threadIdx.x;
    size_t i = q * 8;
    if (i >= (size_t)NROWS * IN_F) return;
    int row = (int)(i >> 11);
    int k8  = (int)((i & 2047) >> 3);

    float4 a = *(const float4*)(x + i);
    float4 b = *(const float4*)(x + i + 4);
    __half2 h0 = __floats2half2_rn(a.x, a.y);
    __half2 h1 = __floats2half2_rn(a.z, a.w);
    __half2 h2 = __floats2half2_rn(b.x, b.y);
    __half2 h3 = __floats2half2_rn(b.z, b.w);
    uint4 p;
    p.x = *(uint32_t*)&h0; p.y = *(uint32_t*)&h1;
    p.z = *(uint32_t*)&h2; p.w = *(uint32_t*)&h3;
    *(uint4*)(Xh + tiled_off(row, k8)) = p;
}

// ---------------------------------------------------------------------------
// Fused GEMM: full/empty mbarrier ring, no per-stage __syncthreads
// ---------------------------------------------------------------------------
__device__ __forceinline__ void issue_stage(uint32_t smem_u32, uint32_t mbarF_u32, int s,
                                            const __half* gA, const __half* gBk,
                                            const __half* gBm) {
    const int b = s & 3;
    const uint32_t mb  = mbarF_u32 + b * 8;
    const uint32_t dst = smem_u32 + b * STAGE_BYTES;
    mbar_expect_tx(mb, STAGE_BYTES);
    bulk_g2s(dst,         gA  + (size_t)s * TILE_HALFS, TILE_BYTES, mb);
    bulk_g2s(dst + 16384, gBk + (size_t)s * TILE_HALFS, TILE_BYTES, mb);
    bulk_g2s(dst + 32768, gBm + (size_t)s * TILE_HALFS, TILE_BYTES, mb);
}

__global__ __launch_bounds__(256, 1) void gemm_fused(
    const float* __restrict__ gate,
    float* __restrict__ outFinal,
    float* __restrict__ outScores,
    float* __restrict__ outMasked)
{
    extern __shared__ char smem[];
    __shared__ float gateS[BN];
    __shared__ __align__(8) uint64_t mbarF[NBUF];
    __shared__ __align__(8) uint64_t mbarE[NBUF];

    const uint32_t smem_u32  = (uint32_t)__cvta_generic_to_shared(smem);
    const uint32_t mbarF_u32 = (uint32_t)__cvta_generic_to_shared(mbarF);
    const uint32_t mbarE_u32 = (uint32_t)__cvta_generic_to_shared(mbarE);

    const int tid    = threadIdx.x;
    const int lane   = tid & 31;
    const int wid    = tid >> 5;
    const int warp_m = wid >> 2;      // 0..1 -> 64 rows
    const int warp_n = wid & 3;       // 0..3 -> 32 cols
    const int mblk = blockIdx.y;
    const int nblk = blockIdx.x;
    const int bm = mblk * BM;
    const int bn = nblk * BN;

    if (tid < BN) gateS[tid] = gate[bn + tid];
    if (tid == 0) {
        #pragma unroll
        for (int b = 0; b < NBUF; b++) {
            mbar_init(mbarF_u32 + b * 8, 1);
            mbar_init(mbarE_u32 + b * 8, 8);   // one arrive per warp
        }
    }
    __syncthreads();

    const __half* gA  = Xh + (size_t)mblk * NSTG * TILE_HALFS;
    const __half* gBk = Wh + (size_t)nblk * NSTG * TILE_HALFS;
    const __half* gBm = gBk + MU_BASE;

    if (tid == 0) {
        issue_stage(smem_u32, mbarF_u32, 0, gA, gBk, gBm);
        issue_stage(smem_u32, mbarF_u32, 1, gA, gBk, gBm);
        issue_stage(smem_u32, mbarF_u32, 2, gA, gBk, gBm);
    }

    float acck[4][4][4], accm[4][4][4];
    #pragma unroll
    for (int mt = 0; mt < 4; mt++)
        #pragma unroll
        for (int nt = 0; nt < 4; nt++)
            #pragma unroll
            for (int q = 0; q < 4; q++) { acck[mt][nt][q] = 0.f; accm[mt][nt][q] = 0.f; }

    const int a_row = lane & 15;
    const int a_sel = lane >> 4;
    const int b_row = (lane & 7) + ((lane & 16) >> 1);
    const int b_sel = (lane & 8) ? 1 : 0;

    for (int s = 0; s < NSTG; s++) {
        const int b = s & 3;

        // Producer: refill buffer (s+3)&3 once all warps emptied it (round r-1).
        if (tid == 0 && s + 3 < NSTG) {
            const int t  = s + 3;
            const int tr = t >> 2;
            mbar_wait(mbarE_u32 + (t & 3) * 8, (tr & 1) ^ 1);
            issue_stage(smem_u32, mbarF_u32, t, gA, gBk, gBm);
        }

        // Consumer: wait for this stage's data.
        mbar_wait(mbarF_u32 + b * 8, (s >> 2) & 1);

        const uint32_t sA  = smem_u32 + b * STAGE_BYTES;
        const uint32_t sBk = sA + 16384;
        const uint32_t sBm = sA + 32768;

        #pragma unroll
        for (int ks = 0; ks < 4; ks++) {
            uint32_t af[4][4];
            #pragma unroll
            for (int mt = 0; mt < 4; mt++) {
                int row = warp_m * 64 + mt * 16 + a_row;
                int ch  = (ks * 2 + a_sel) ^ (row & 7);
                ldmatrix_x4(af[mt], sA + row * 128 + ch * 16);
            }
            uint32_t bk[4][2], bmu[4][2];
            #pragma unroll
            for (int bt = 0; bt < 2; bt++) {
                int row = warp_n * 32 + bt * 16 + b_row;
                int ch  = (ks * 2 + b_sel) ^ (row & 7);
                uint32_t r[4];
                ldmatrix_x4(r, sBk + row * 128 + ch * 16);
                bk[2*bt  ][0] = r[0]; bk[2*bt  ][1] = r[1];
                bk[2*bt+1][0] = r[2]; bk[2*bt+1][1] = r[3];
                uint32_t t[4];
                ldmatrix_x4(t, sBm + row * 128 + ch * 16);
                bmu[2*bt  ][0] = t[0]; bmu[2*bt  ][1] = t[1];
                bmu[2*bt+1][0] = t[2]; bmu[2*bt+1][1] = t[3];
            }
            #pragma unroll
            for (int mt = 0; mt < 4; mt++) {
                #pragma unroll
                for (int nt = 0; nt < 4; nt++) {
                    mma16816(acck[mt][nt], af[mt], bk[nt]);
                    mma16816(accm[mt][nt], af[mt], bmu[nt]);
                }
            }
        }

        // Warp done reading buffer b.
        if (lane == 0) mbar_arrive(mbarE_u32 + b * 8);
    }

    // Fused epilogue
    #pragma unroll
    for (int mt = 0; mt < 4; mt++) {
        int r0 = bm + warp_m * 64 + mt * 16 + (lane >> 2);
        #pragma unroll
        for (int nt = 0; nt < 4; nt++) {
            int cl = warp_n * 32 + nt * 8 + (lane & 3) * 2;
            int c  = bn + cl;
            float g0 = gateS[cl], g1 = gateS[cl + 1];

            float s0 = acck[mt][nt][0] * INV_SQRT_D;
            float s1 = acck[mt][nt][1] * INV_SQRT_D;
            float m0 = accm[mt][nt][0] * fmaxf(s0 - g0, 0.f);
            float m1 = accm[mt][nt][1] * fmaxf(s1 - g1, 0.f);
            size_t o0 = (size_t)r0 * OUT_F + c;
            *(float2*)(outScores + o0) = make_float2(s0, s1);
            *(float2*)(outFinal  + o0) = make_float2(m0, m1);
            *(float2*)(outMasked + o0) = make_float2(m0, m1);

            float s2 = acck[mt][nt][2] * INV_SQRT_D;
            float s3 = acck[mt][nt][3] * INV_SQRT_D;
            float m2 = accm[mt][nt][2] * fmaxf(s2 - g0, 0.f);
            float m3 = accm[mt][nt][3] * fmaxf(s3 - g1, 0.f);
            size_t o1 = (size_t)(r0 + 8) * OUT_F + c;
            *(float2*)(outScores + o1) = make_float2(s2, s3);
            *(float2*)(outFinal  + o1) = make_float2(m2, m3);
            *(float2*)(outMasked + o1) = make_float2(m2, m3);
        }
    }
}

// ---------------------------------------------------------------------------
// Launch
// ---------------------------------------------------------------------------
extern "C" void kernel_launch(void* const* d_in, const int* in_sizes, int n_in,
                              void* d_out, int out_size) {
    const float* x     = (const float*)d_in[0];
    const float* mu    = (const float*)d_in[1];
    const float* sigma = (const float*)d_in[2];
    const float* gate  = (const float*)d_in[3];

    float* out  = (float*)d_out;
    float* out0 = out;                               // final_output
    float* out1 = out + (size_t)NROWS * OUT_F;       // scores
    float* out2 = out + 2 * (size_t)NROWS * OUT_F;   // masked_output

    prep_w<<<(OUT_F * IN_F / 8 + 255) / 256, 256>>>(mu, sigma);
    prep_x<<<(unsigned)(((size_t)NROWS * IN_F / 8 + 255) / 256), 256>>>(x);

    cudaFuncSetAttribute(gemm_fused, cudaFuncAttributeMaxDynamicSharedMemorySize, SMEM_TOTAL);
    dim3 grid(OUT_F / BN, NROWS / BM);               // (16, 64) = 1024 CTAs
    gemm_fused<<<grid, 256, SMEM_TOTAL>>>(gate, out0, out1, out2);
}